// round 1
// baseline (speedup 1.0000x reference)
#include <cuda_runtime.h>
#include <cstdint>

// ---------------------------------------------------------------------------
// Problem constants
// ---------------------------------------------------------------------------
#define T_STEPS   512
#define IN_DIM    1024
#define ISD       32
#define DGRID     256
#define OUT_DIM   128
#define NPIX      (DGRID * DGRID)          // 65536
#define KTOT      (2 * NPIX)               // 131072

// GEMM split-K config
#define SPLITK    64
#define KSLICE    (KTOT / SPLITK)          // 2048

// ---------------------------------------------------------------------------
// Device scratch (static allocations only — no cudaMalloc allowed)
// ---------------------------------------------------------------------------
__device__ int      g_perm[IN_DIM];
__device__ float    g_wval[IN_DIM];
__device__ float    g_tanhu[T_STEPS * IN_DIM];                 // 2 MB
__device__ unsigned g_Sbits[2][DGRID][8];                      // double-buffered S bitmask
__device__ int      g_prog[128 * 32];                          // per-block progress (128B stride)
__device__ float    g_outs[(size_t)T_STEPS * KTOT];            // 268 MB  [t][ch][y][x]
__device__ float    g_part[(size_t)SPLITK * T_STEPS * OUT_DIM];// 16.8 MB split-K partials

__constant__ int c_nboff[8] = {-4, -3, -2, -1, 1, 2, 3, 4};

// ---------------------------------------------------------------------------
// Kernel 0: reset sync state (runs every graph replay)
// ---------------------------------------------------------------------------
__global__ void init_kernel() {
    int i = blockIdx.x * blockDim.x + threadIdx.x;
    if (i < 128 * 32) g_prog[i] = 0;
    if (i < 2 * DGRID * 8) ((unsigned*)g_Sbits)[i] = 0u;
}

// ---------------------------------------------------------------------------
// Kernel 1: discover permutation from the (permuted-identity) embed matrix
// ---------------------------------------------------------------------------
__global__ void perm_kernel(const float* __restrict__ We) {
    int row = blockIdx.x;                     // 0..1023
    for (int j = threadIdx.x; j < IN_DIM; j += blockDim.x) {
        float w = We[row * IN_DIM + j];
        if (fabsf(w) > 0.5f) { g_perm[row] = j; g_wval[row] = w; }
    }
}

// ---------------------------------------------------------------------------
// Kernel 2: tanhu[t, ci] = tanh(mask_coarse[ci] * (X[t, perm[ci]] * wval[ci]))
// ---------------------------------------------------------------------------
__global__ void tanhu_kernel(const float* __restrict__ X,
                             const float* __restrict__ mc) {
    int idx = blockIdx.x * blockDim.x + threadIdx.x;   // < 512*1024
    if (idx >= T_STEPS * IN_DIM) return;
    int t  = idx >> 10;
    int ci = idx & 1023;
    float v = X[(t << 10) + g_perm[ci]] * g_wval[ci];
    g_tanhu[idx] = tanhf(__fmul_rn(mc[ci], v));
}

// ---------------------------------------------------------------------------
// Kernel 3: persistent reservoir scan.
// 128 blocks x 512 threads; block b owns rows 2b, 2b+1; 1 thread per pixel.
// S packed as 256-bit row bitmasks, lateral sums via funnelshift+popc (exact).
// Neighbor-only point-to-point sync through L2 progress counters.
// ---------------------------------------------------------------------------
__global__ void __launch_bounds__(512, 1)
scan_kernel(const float* __restrict__ mask_fine) {
    const int b   = blockIdx.x;          // 0..127
    const int tid = threadIdx.x;
    const int dy  = tid >> 8;            // 0/1
    const int x   = tid & 255;
    const int y   = (b << 1) + dy;
    const int ci  = ((y >> 3) << 5) + (x >> 3);
    const float mf = mask_fine[(y << 8) + x];

    __shared__ unsigned sS[18][8];       // rows r0-8 .. r0+9

    // precompute circular window params (depend only on x)
    const int b5 = (x - 2) & 255, w5 = b5 >> 5, o5 = b5 & 31, w5b = (w5 + 1) & 7;
    const int b9 = (x - 8) & 255, w9 = b9 >> 5, o9 = b9 & 31, w9b = (w9 + 1) & 7;

    const int base_row = ((b << 1) - 8) & 255;
    const int krow = 8 + dy;             // smem row index of this thread's own row

    // my polling target (threads 0..7 poll one neighbor each)
    volatile int* pollp = nullptr;
    if (tid < 8) {
        int nb = (b + c_nboff[tid]) & 127;
        pollp = (volatile int*)&g_prog[nb << 5];
    }

    float V = 0.0f;

    for (int t = 0; t < T_STEPS; ++t) {
        // independent work first: input drive + decay
        float u  = __fmul_rn(mf, __ldg(&g_tanhu[(t << 10) + ci]));
        float Vd = __fadd_rn(__fmul_rn(0.9f, V), __fmul_rn(0.5f, u));

        // wait for neighbor blocks to finish step t-1 (also licenses our write
        // of buffer t&1: neighbors completed their reads of it at step t-1)
        if (tid < 8) { while (*pollp < t) { } }
        __syncthreads();

        // stage previous-step S bitmask rows (L2, bypass L1)
        const unsigned pbuf = (unsigned)((t & 1) ^ 1);
        if (tid < 144) {
            int k = tid >> 3, w = tid & 7;
            int row = (base_row + k) & 255;
            sS[k][w] = __ldcg(&g_Sbits[pbuf][row][w]);
        }
        __syncthreads();

        // exact integer lateral sums via popcount
        int n5 = 0;
#pragma unroll
        for (int d = -2; d <= 2; ++d) {
            unsigned v = __funnelshift_r(sS[krow + d][w5], sS[krow + d][w5b], o5);
            n5 += __popc(v & 0x1Fu);
        }
        int n9 = 0;
#pragma unroll
        for (int d = -8; d <= 8; d += 2) {
            unsigned v = __funnelshift_r(sS[krow + d][w9], sS[krow + d][w9b], o9);
            n9 += __popc(v & 0x15555u);
        }
        float c5  = __fmul_rn((float)n5, 1.0f / 25.0f);
        float c9  = __fmul_rn((float)n9, 1.0f / 81.0f);
        float lat = __fadd_rn(c5, __fmul_rn(-0.5f, c9));

        // membrane update (mirrors reference op order)
        float Vn = Vd;
        if (Vd >= 0.1f)
            Vn = __fadd_rn(__fadd_rn(Vd, __fmul_rn(0.5f, u)), lat);
        Vn = fminf(Vn, 1.0f);
        bool  Sb = (Vn > 0.75f);
        if (Sb) Vn = 0.0f;
        V = Vn;
        float Sf = Sb ? 1.0f : 0.0f;

        // stream outs for the readout GEMM: [t][ch][y][x]
        size_t obase = (size_t)t * KTOT + ((size_t)y << 8) + x;
        g_outs[obase]        = Vn;
        g_outs[obase + NPIX] = Sf;

        // publish new S bitmask (buffer t&1)
        unsigned ball = __ballot_sync(0xffffffffu, Sb);
        if ((x & 31) == 0) g_Sbits[t & 1][y][x >> 5] = ball;

        __threadfence();              // order S stores before progress flag
        __syncthreads();
        if (tid == 0) *((volatile int*)&g_prog[b << 5]) = t + 1;
    }
}

// ---------------------------------------------------------------------------
// Kernel 4: split-K fp32 GEMM  C[512,128] = outs[512,K] * W[128,K]^T (partials)
// BM=128, BN=128, BK=8, 256 threads, 8x8 per thread (split-4 layout,
// conflict-free LDS.128 reads).
// ---------------------------------------------------------------------------
__global__ void __launch_bounds__(256)
gemm_kernel(const float* __restrict__ W) {
    __shared__ float As[8][132];
    __shared__ float Bs[8][132];

    const int mt  = blockIdx.x;          // 0..3  (M tiles of 128)
    const int ks  = blockIdx.y;          // 0..SPLITK-1
    const int tid = threadIdx.x;
    const int tr  = tid >> 4;            // 0..15
    const int tc  = tid & 15;            // 0..15
    const int lr  = tid >> 1;            // 0..127 (load row)
    const int lk  = (tid & 1) << 2;      // 0 or 4 (load k group)

    const float* Ap = g_outs + (size_t)(mt * 128 + lr) * KTOT + (size_t)ks * KSLICE + lk;
    const float* Bp = W      + (size_t)lr * KTOT            + (size_t)ks * KSLICE + lk;

    float acc[8][8];
#pragma unroll
    for (int i = 0; i < 8; ++i)
#pragma unroll
        for (int j = 0; j < 8; ++j) acc[i][j] = 0.0f;

    for (int kk = 0; kk < KSLICE; kk += 8) {
        float4 a  = *reinterpret_cast<const float4*>(Ap + kk);
        float4 bv = *reinterpret_cast<const float4*>(Bp + kk);
        __syncthreads();
        As[lk + 0][lr] = a.x;  As[lk + 1][lr] = a.y;
        As[lk + 2][lr] = a.z;  As[lk + 3][lr] = a.w;
        Bs[lk + 0][lr] = bv.x; Bs[lk + 1][lr] = bv.y;
        Bs[lk + 2][lr] = bv.z; Bs[lk + 3][lr] = bv.w;
        __syncthreads();
#pragma unroll
        for (int k = 0; k < 8; ++k) {
            float ar[8], br[8];
#pragma unroll
            for (int i = 0; i < 4; ++i) {
                ar[i]     = As[k][tr * 4 + i];
                ar[i + 4] = As[k][64 + tr * 4 + i];
                br[i]     = Bs[k][tc * 4 + i];
                br[i + 4] = Bs[k][64 + tc * 4 + i];
            }
#pragma unroll
            for (int i = 0; i < 8; ++i)
#pragma unroll
                for (int j = 0; j < 8; ++j)
                    acc[i][j] = fmaf(ar[i], br[j], acc[i][j]);
        }
    }

#pragma unroll
    for (int i = 0; i < 8; ++i) {
        int m = mt * 128 + ((i < 4) ? (tr * 4 + i) : (64 + tr * 4 + (i - 4)));
#pragma unroll
        for (int j = 0; j < 8; ++j) {
            int n = (j < 4) ? (tc * 4 + j) : (64 + tc * 4 + (j - 4));
            g_part[((size_t)ks * T_STEPS + m) * OUT_DIM + n] = acc[i][j];
        }
    }
}

// ---------------------------------------------------------------------------
// Kernel 5: deterministic split-K reduction + bias
// ---------------------------------------------------------------------------
__global__ void reduce_kernel(const float* __restrict__ b_out,
                              float* __restrict__ out) {
    int i = blockIdx.x * blockDim.x + threadIdx.x;   // < 512*128
    if (i >= T_STEPS * OUT_DIM) return;
    int o = i & (OUT_DIM - 1);
    float s = 0.0f;
#pragma unroll 8
    for (int ks = 0; ks < SPLITK; ++ks)
        s += g_part[(size_t)ks * (T_STEPS * OUT_DIM) + i];
    out[i] = s + b_out[o];
}

// ---------------------------------------------------------------------------
// Launch
// ---------------------------------------------------------------------------
extern "C" void kernel_launch(void* const* d_in, const int* in_sizes, int n_in,
                              void* d_out, int out_size) {
    const float* X  = (const float*)d_in[0];   // [512,1024]
    const float* We = (const float*)d_in[1];   // [1024,1024]
    const float* mc = (const float*)d_in[2];   // [1,1,32,32]
    const float* mf = (const float*)d_in[3];   // [1,1,256,256]
    const float* W  = (const float*)d_in[4];   // [128,2,256,256]
    const float* bo = (const float*)d_in[5];   // [128]
    float* out = (float*)d_out;                // [512,128]

    init_kernel<<<32, 256>>>();
    perm_kernel<<<IN_DIM, 256>>>(We);
    tanhu_kernel<<<(T_STEPS * IN_DIM + 255) / 256, 256>>>(X, mc);
    scan_kernel<<<128, 512>>>(mf);
    dim3 ggrid(4, SPLITK);
    gemm_kernel<<<ggrid, 256>>>(W);
    reduce_kernel<<<(T_STEPS * OUT_DIM + 255) / 256, 256>>>(bo, out);
}

// round 3
// speedup vs baseline: 1.1161x; 1.1161x over previous
#include <cuda_runtime.h>
#include <cuda_bf16.h>
#include <cstdint>

// ---------------------------------------------------------------------------
// Problem constants
// ---------------------------------------------------------------------------
#define T_STEPS   512
#define IN_DIM    1024
#define DGRID     256
#define OUT_DIM   128
#define NPIX      (DGRID * DGRID)          // 65536
#define KTOT      (2 * NPIX)               // 131072  (V,S channels)

// GEMM tiling / split-K
#define BM        128
#define BN        128
#define BK        32
#define NSLICES   16                       // slices per segment over KTOT
#define GSLICE    (KTOT / NSLICES)         // 8192
#define KITERS    (GSLICE / BK)            // 256
// segments: 0 = Ahi*Whi (16 slices), 1 = Ahi*Wlo (16), 2 = Alo*Whi (8: V region only)
#define NSEG_TOT  40

// ---------------------------------------------------------------------------
// Device scratch (static allocations only)
// ---------------------------------------------------------------------------
__device__ int            g_perm[IN_DIM];
__device__ float          g_wval[IN_DIM];
__device__ float          g_tanhu[T_STEPS * IN_DIM];
__device__ unsigned       g_Sbits[2][DGRID][8];
__device__ int            g_prog[128 * 32];
__device__ __nv_bfloat16  g_Ahi[(size_t)T_STEPS * KTOT];   // [t][ch][pix]
__device__ __nv_bfloat16  g_Alo[(size_t)T_STEPS * KTOT];   // S half stays 0
__device__ __nv_bfloat16  g_Whi[(size_t)OUT_DIM * KTOT];
__device__ __nv_bfloat16  g_Wlo[(size_t)OUT_DIM * KTOT];
__device__ float          g_part[(size_t)NSEG_TOT * T_STEPS * OUT_DIM];

__constant__ int c_nboff[8] = {-4, -3, -2, -1, 1, 2, 3, 4};

// ---------------------------------------------------------------------------
// PTX helpers (all plain sm_80+ features -> safe for .target sm_103)
// ---------------------------------------------------------------------------
__device__ __forceinline__ uint32_t smem_u32(const void* p) {
    return (uint32_t)__cvta_generic_to_shared(p);
}
__device__ __forceinline__ void cp_async16(uint32_t saddr, const void* gaddr) {
    asm volatile("cp.async.cg.shared.global [%0], [%1], 16;" :: "r"(saddr), "l"(gaddr));
}
__device__ __forceinline__ void cp_commit() {
    asm volatile("cp.async.commit_group;" ::: "memory");
}
__device__ __forceinline__ void cp_wait1() {
    asm volatile("cp.async.wait_group 1;" ::: "memory");
}
__device__ __forceinline__ void cp_wait0() {
    asm volatile("cp.async.wait_group 0;" ::: "memory");
}
__device__ __forceinline__ void ldsm_x4(uint32_t& r0, uint32_t& r1, uint32_t& r2,
                                        uint32_t& r3, uint32_t addr) {
    asm volatile("ldmatrix.sync.aligned.m8n8.x4.shared.b16 {%0,%1,%2,%3}, [%4];"
                 : "=r"(r0), "=r"(r1), "=r"(r2), "=r"(r3) : "r"(addr));
}
__device__ __forceinline__ void mma_bf16(float* d, const uint32_t* a, const uint32_t* b) {
    asm volatile(
        "mma.sync.aligned.m16n8k16.row.col.f32.bf16.bf16.f32 "
        "{%0,%1,%2,%3}, {%4,%5,%6,%7}, {%8,%9}, {%0,%1,%2,%3};"
        : "+f"(d[0]), "+f"(d[1]), "+f"(d[2]), "+f"(d[3])
        : "r"(a[0]), "r"(a[1]), "r"(a[2]), "r"(a[3]), "r"(b[0]), "r"(b[1]));
}

// ---------------------------------------------------------------------------
// Kernel 0: reset sync state
// ---------------------------------------------------------------------------
__global__ void init_kernel() {
    int i = blockIdx.x * blockDim.x + threadIdx.x;
    if (i < 128 * 32) g_prog[i] = 0;
    if (i < 2 * DGRID * 8) ((unsigned*)g_Sbits)[i] = 0u;
}

// ---------------------------------------------------------------------------
// Kernel 1: discover permutation from the permuted-identity embed matrix
// ---------------------------------------------------------------------------
__global__ void perm_kernel(const float* __restrict__ We) {
    int row = blockIdx.x;
    for (int j = threadIdx.x; j < IN_DIM; j += blockDim.x) {
        float w = We[row * IN_DIM + j];
        if (fabsf(w) > 0.5f) { g_perm[row] = j; g_wval[row] = w; }
    }
}

// ---------------------------------------------------------------------------
// Kernel 2: tanhu[t, ci] = tanh(mask_coarse[ci] * X[t, perm[ci]])
// ---------------------------------------------------------------------------
__global__ void tanhu_kernel(const float* __restrict__ X,
                             const float* __restrict__ mc) {
    int idx = blockIdx.x * blockDim.x + threadIdx.x;
    if (idx >= T_STEPS * IN_DIM) return;
    int t  = idx >> 10;
    int ci = idx & 1023;
    float v = X[(t << 10) + g_perm[ci]] * g_wval[ci];
    g_tanhu[idx] = tanhf(__fmul_rn(mc[ci], v));
}

// ---------------------------------------------------------------------------
// Kernel 2b: split W into bf16 hi/lo
// ---------------------------------------------------------------------------
__global__ void wsplit_kernel(const float* __restrict__ W) {
    int i = blockIdx.x * blockDim.x + threadIdx.x;
    if (i >= OUT_DIM * KTOT) return;
    float w = W[i];
    __nv_bfloat16 h = __float2bfloat16(w);
    g_Whi[i] = h;
    g_Wlo[i] = __float2bfloat16(w - __bfloat162float(h));
}

// ---------------------------------------------------------------------------
// Kernel 3: persistent reservoir scan (bit-packed S, popcount lateral sums,
// neighbor-only L2 sync).  Publishes S bitmask + sync flag BEFORE streaming
// outputs so the per-step fence drains only 16 words, not the output stream.
// ---------------------------------------------------------------------------
__global__ void __launch_bounds__(512, 1)
scan_kernel(const float* __restrict__ mask_fine) {
    const int b   = blockIdx.x;
    const int tid = threadIdx.x;
    const int dy  = tid >> 8;
    const int x   = tid & 255;
    const int y   = (b << 1) + dy;
    const int ci  = ((y >> 3) << 5) + (x >> 3);
    const float mf = mask_fine[(y << 8) + x];

    __shared__ unsigned sS[18][8];

    const int b5 = (x - 2) & 255, w5 = b5 >> 5, o5 = b5 & 31, w5b = (w5 + 1) & 7;
    const int b9 = (x - 8) & 255, w9 = b9 >> 5, o9 = b9 & 31, w9b = (w9 + 1) & 7;

    const int base_row = ((b << 1) - 8) & 255;
    const int krow = 8 + dy;
    const int pix  = (y << 8) + x;

    volatile int* pollp = nullptr;
    if (tid < 8) {
        int nb = (b + c_nboff[tid]) & 127;
        pollp = (volatile int*)&g_prog[nb << 5];
    }

    float V = 0.0f;

    for (int t = 0; t < T_STEPS; ++t) {
        float u  = __fmul_rn(mf, __ldg(&g_tanhu[(t << 10) + ci]));
        float Vd = __fadd_rn(__fmul_rn(0.9f, V), __fmul_rn(0.5f, u));

        if (tid < 8) { while (*pollp < t) { } }
        __syncthreads();

        const unsigned pbuf = (unsigned)((t & 1) ^ 1);
        if (tid < 144) {
            int k = tid >> 3, w = tid & 7;
            int row = (base_row + k) & 255;
            sS[k][w] = __ldcg(&g_Sbits[pbuf][row][w]);
        }
        __syncthreads();

        int n5 = 0;
#pragma unroll
        for (int d = -2; d <= 2; ++d) {
            unsigned v = __funnelshift_r(sS[krow + d][w5], sS[krow + d][w5b], o5);
            n5 += __popc(v & 0x1Fu);
        }
        int n9 = 0;
#pragma unroll
        for (int d = -8; d <= 8; d += 2) {
            unsigned v = __funnelshift_r(sS[krow + d][w9], sS[krow + d][w9b], o9);
            n9 += __popc(v & 0x15555u);
        }
        float c5  = __fmul_rn((float)n5, 1.0f / 25.0f);
        float c9  = __fmul_rn((float)n9, 1.0f / 81.0f);
        float lat = __fadd_rn(c5, __fmul_rn(-0.5f, c9));

        float Vn = Vd;
        if (Vd >= 0.1f)
            Vn = __fadd_rn(__fadd_rn(Vd, __fmul_rn(0.5f, u)), lat);
        Vn = fminf(Vn, 1.0f);
        bool Sb = (Vn > 0.75f);
        if (Sb) Vn = 0.0f;
        V = Vn;

        // publish S bitmask + flag first (critical path), outputs after
        unsigned ball = __ballot_sync(0xffffffffu, Sb);
        if ((x & 31) == 0) g_Sbits[t & 1][y][x >> 5] = ball;
        __threadfence();
        __syncthreads();
        if (tid == 0) *((volatile int*)&g_prog[b << 5]) = t + 1;

        // stream split-precision outputs (off the sync critical path)
        __nv_bfloat16 vh = __float2bfloat16(Vn);
        float vlo = Vn - __bfloat162float(vh);
        size_t obase = (size_t)t * KTOT + pix;
        g_Ahi[obase]        = vh;
        g_Ahi[obase + NPIX] = Sb ? __float2bfloat16(1.0f) : __float2bfloat16(0.0f);
        g_Alo[obase]        = __float2bfloat16(vlo);   // S-lo region never written: stays 0
    }
}

// ---------------------------------------------------------------------------
// Kernel 4: bf16 HMMA split-K GEMM via ldmatrix + mma.sync (sm_103-safe).
// grid = (4 M-tiles, 40 segments/slices).  BM=128, BN=128, BK=32, 256 thr,
// warp tile 32x64, double-buffered cp.async, padded smem (stride 40 bf16).
// ---------------------------------------------------------------------------
__global__ void __launch_bounds__(256)
mma_gemm_kernel() {
    __shared__ __nv_bfloat16 sA[2][BM][BK + 8];
    __shared__ __nv_bfloat16 sB[2][BN][BK + 8];

    const int mt = blockIdx.x;           // 0..3
    const int s  = blockIdx.y;           // 0..39
    int seg, slice;
    if (s < 16)      { seg = 0; slice = s; }
    else if (s < 32) { seg = 1; slice = s - 16; }
    else             { seg = 2; slice = s - 32; }    // only V-region slices
    const size_t k0 = (size_t)slice * GSLICE;

    const __nv_bfloat16* Abase = (seg == 2) ? g_Alo : g_Ahi;
    const __nv_bfloat16* Bbase = (seg == 1) ? g_Wlo : g_Whi;

    const int tid  = threadIdx.x;
    const int wid  = tid >> 5;
    const int lane = tid & 31;
    const int wm   = wid >> 1;           // 0..3  -> rows wm*32
    const int wn   = wid & 1;            // 0..1  -> cols wn*64

    // ---- load mapping: thread -> (row, two 16B chunks) for both tiles
    const int lrow = tid >> 1;
    const int lch  = (tid & 1) << 1;     // chunk index 0 or 2 (each 8 bf16)
    const __nv_bfloat16* gA = Abase + (size_t)(mt * BM + lrow) * KTOT + k0 + lch * 8;
    const __nv_bfloat16* gB = Bbase + (size_t)lrow * KTOT + k0 + lch * 8;
    const uint32_t sA0 = smem_u32(&sA[0][0][0]);
    const uint32_t sB0 = smem_u32(&sB[0][0][0]);
    const uint32_t bufBytes = (uint32_t)BM * (BK + 8) * 2;
    const uint32_t rowOffA = ((uint32_t)lrow * (BK + 8) + lch * 8) * 2;
    const uint32_t rowOffB = rowOffA;

    // ---- ldmatrix lane addressing (constant per lane)
    const int aRow = wm * 32 + (lane & 15);
    const int aK   = (lane >> 4) << 3;
    const int bRow = wn * 64 + (lane & 7) + ((lane >> 4) << 3);
    const int bK   = ((lane >> 3) & 1) << 3;

    float d[2][8][4];
#pragma unroll
    for (int mi = 0; mi < 2; ++mi)
#pragma unroll
        for (int ni = 0; ni < 8; ++ni)
#pragma unroll
            for (int r = 0; r < 4; ++r) d[mi][ni][r] = 0.0f;

    // prologue: fill buffer 0
    {
        cp_async16(sA0 + rowOffA, gA);
        cp_async16(sA0 + rowOffA + 16, gA + 8);
        cp_async16(sB0 + rowOffB, gB);
        cp_async16(sB0 + rowOffB + 16, gB + 8);
        cp_commit();
    }

    for (int it = 0; it < KITERS; ++it) {
        const int cb = it & 1;
        if (it + 1 < KITERS) {
            const int nb = (it + 1) & 1;
            const __nv_bfloat16* ga = gA + (size_t)(it + 1) * BK;
            const __nv_bfloat16* gb = gB + (size_t)(it + 1) * BK;
            cp_async16(sA0 + nb * bufBytes + rowOffA, ga);
            cp_async16(sA0 + nb * bufBytes + rowOffA + 16, ga + 8);
            cp_async16(sB0 + nb * bufBytes + rowOffB, gb);
            cp_async16(sB0 + nb * bufBytes + rowOffB + 16, gb + 8);
            cp_commit();
            cp_wait1();
        } else {
            cp_wait0();
        }
        __syncthreads();

#pragma unroll
        for (int ks = 0; ks < 2; ++ks) {           // k16 sub-steps
            const int kc = ks * 16;
            uint32_t a[2][4], bf[4][4];
#pragma unroll
            for (int mi = 0; mi < 2; ++mi) {
                uint32_t addr = sA0 + cb * bufBytes +
                    ((uint32_t)(aRow + mi * 16) * (BK + 8) + kc + aK) * 2;
                ldsm_x4(a[mi][0], a[mi][1], a[mi][2], a[mi][3], addr);
            }
#pragma unroll
            for (int g = 0; g < 4; ++g) {
                uint32_t addr = sB0 + cb * bufBytes +
                    ((uint32_t)(bRow + g * 16) * (BK + 8) + kc + bK) * 2;
                ldsm_x4(bf[g][0], bf[g][1], bf[g][2], bf[g][3], addr);
            }
#pragma unroll
            for (int mi = 0; mi < 2; ++mi)
#pragma unroll
                for (int g = 0; g < 4; ++g) {
                    mma_bf16(d[mi][g * 2 + 0], a[mi], &bf[g][0]);
                    mma_bf16(d[mi][g * 2 + 1], a[mi], &bf[g][2]);
                }
        }
        __syncthreads();
    }

    // epilogue -> g_part[s][m][n]
#pragma unroll
    for (int mi = 0; mi < 2; ++mi) {
        const int m0 = mt * BM + wm * 32 + mi * 16 + (lane >> 2);
#pragma unroll
        for (int ni = 0; ni < 8; ++ni) {
            const int col = wn * 64 + ni * 8 + (lane & 3) * 2;
            float2 v01 = make_float2(d[mi][ni][0], d[mi][ni][1]);
            float2 v23 = make_float2(d[mi][ni][2], d[mi][ni][3]);
            *reinterpret_cast<float2*>(
                &g_part[((size_t)s * T_STEPS + m0) * OUT_DIM + col]) = v01;
            *reinterpret_cast<float2*>(
                &g_part[((size_t)s * T_STEPS + m0 + 8) * OUT_DIM + col]) = v23;
        }
    }
}

// ---------------------------------------------------------------------------
// Kernel 5: deterministic split-K reduction + bias
// ---------------------------------------------------------------------------
__global__ void reduce_kernel(const float* __restrict__ b_out,
                              float* __restrict__ out) {
    int i = blockIdx.x * blockDim.x + threadIdx.x;
    if (i >= T_STEPS * OUT_DIM) return;
    int o = i & (OUT_DIM - 1);
    float sum = 0.0f;
#pragma unroll 8
    for (int ks = 0; ks < NSEG_TOT; ++ks)
        sum += g_part[(size_t)ks * (T_STEPS * OUT_DIM) + i];
    out[i] = sum + b_out[o];
}

// ---------------------------------------------------------------------------
// Launch
// ---------------------------------------------------------------------------
extern "C" void kernel_launch(void* const* d_in, const int* in_sizes, int n_in,
                              void* d_out, int out_size) {
    const float* X  = (const float*)d_in[0];   // [512,1024]
    const float* We = (const float*)d_in[1];   // [1024,1024]
    const float* mc = (const float*)d_in[2];   // [1,1,32,32]
    const float* mf = (const float*)d_in[3];   // [1,1,256,256]
    const float* W  = (const float*)d_in[4];   // [128,2,256,256]
    const float* bo = (const float*)d_in[5];   // [128]
    float* out = (float*)d_out;                // [512,128]

    init_kernel<<<32, 256>>>();
    perm_kernel<<<IN_DIM, 256>>>(We);
    tanhu_kernel<<<(T_STEPS * IN_DIM + 255) / 256, 256>>>(X, mc);
    wsplit_kernel<<<(OUT_DIM * KTOT + 255) / 256, 256>>>(W);
    scan_kernel<<<128, 512>>>(mf);
    dim3 ggrid(4, NSEG_TOT);
    mma_gemm_kernel<<<ggrid, 256>>>();
    reduce_kernel<<<(T_STEPS * OUT_DIM + 255) / 256, 256>>>(bo, out);
}

// round 4
// speedup vs baseline: 1.5434x; 1.3829x over previous
#include <cuda_runtime.h>
#include <cuda_bf16.h>
#include <cstdint>

// ---------------------------------------------------------------------------
// Problem constants
// ---------------------------------------------------------------------------
#define T_STEPS   512
#define IN_DIM    1024
#define DGRID     256
#define OUT_DIM   128
#define NPIX      (DGRID * DGRID)          // 65536
#define KTOT      (2 * NPIX)               // 131072  (V,S channels)

// GEMM tiling / split-K
#define BM        128
#define BN        128
#define BK        32
#define NSLICES   16                       // slices per segment over KTOT
#define GSLICE    (KTOT / NSLICES)         // 8192
#define KITERS    (GSLICE / BK)            // 256
// segments: 0 = Ahi*Whi (16 slices), 1 = Ahi*Wlo (16), 2 = Alo*Whi (8: V region only)
#define NSEG_TOT  40

// ---------------------------------------------------------------------------
// Device scratch (static allocations only)
// ---------------------------------------------------------------------------
__device__ int            g_perm[IN_DIM];
__device__ float          g_wval[IN_DIM];
__device__ float          g_tanhu[T_STEPS * IN_DIM];
// tagged S words: [parity][row][chunk]  = (tag<<32) | ballot(32 px)
__device__ unsigned long long g_S64[2][DGRID][8];
__device__ __nv_bfloat16  g_Ahi[(size_t)T_STEPS * KTOT];   // [t][ch][pix]
__device__ __nv_bfloat16  g_Alo[(size_t)T_STEPS * KTOT];   // S half stays 0
__device__ __nv_bfloat16  g_Whi[(size_t)OUT_DIM * KTOT];
__device__ __nv_bfloat16  g_Wlo[(size_t)OUT_DIM * KTOT];
__device__ float          g_part[(size_t)NSEG_TOT * T_STEPS * OUT_DIM];

// ---------------------------------------------------------------------------
// PTX helpers (plain sm_80+ features -> safe for .target sm_103)
// ---------------------------------------------------------------------------
__device__ __forceinline__ uint32_t smem_u32(const void* p) {
    return (uint32_t)__cvta_generic_to_shared(p);
}
__device__ __forceinline__ void cp_async16(uint32_t saddr, const void* gaddr) {
    asm volatile("cp.async.cg.shared.global [%0], [%1], 16;" :: "r"(saddr), "l"(gaddr));
}
__device__ __forceinline__ void cp_commit() {
    asm volatile("cp.async.commit_group;" ::: "memory");
}
__device__ __forceinline__ void cp_wait1() {
    asm volatile("cp.async.wait_group 1;" ::: "memory");
}
__device__ __forceinline__ void cp_wait0() {
    asm volatile("cp.async.wait_group 0;" ::: "memory");
}
__device__ __forceinline__ void ldsm_x4(uint32_t& r0, uint32_t& r1, uint32_t& r2,
                                        uint32_t& r3, uint32_t addr) {
    asm volatile("ldmatrix.sync.aligned.m8n8.x4.shared.b16 {%0,%1,%2,%3}, [%4];"
                 : "=r"(r0), "=r"(r1), "=r"(r2), "=r"(r3) : "r"(addr));
}
__device__ __forceinline__ void mma_bf16(float* d, const uint32_t* a, const uint32_t* b) {
    asm volatile(
        "mma.sync.aligned.m16n8k16.row.col.f32.bf16.bf16.f32 "
        "{%0,%1,%2,%3}, {%4,%5,%6,%7}, {%8,%9}, {%0,%1,%2,%3};"
        : "+f"(d[0]), "+f"(d[1]), "+f"(d[2]), "+f"(d[3])
        : "r"(a[0]), "r"(a[1]), "r"(a[2]), "r"(a[3]), "r"(b[0]), "r"(b[1]));
}

// ---------------------------------------------------------------------------
// Kernel 0: reset sync state (every graph replay)
// ---------------------------------------------------------------------------
__global__ void init_kernel() {
    int i = blockIdx.x * blockDim.x + threadIdx.x;
    if (i < 2 * DGRID * 8) ((unsigned long long*)g_S64)[i] = 0ull;
}

// ---------------------------------------------------------------------------
// Kernel 1: discover permutation from the permuted-identity embed matrix
// ---------------------------------------------------------------------------
__global__ void perm_kernel(const float* __restrict__ We) {
    int row = blockIdx.x;
    for (int j = threadIdx.x; j < IN_DIM; j += blockDim.x) {
        float w = We[row * IN_DIM + j];
        if (fabsf(w) > 0.5f) { g_perm[row] = j; g_wval[row] = w; }
    }
}

// ---------------------------------------------------------------------------
// Kernel 2: tanhu[t, ci] = tanh(mask_coarse[ci] * X[t, perm[ci]])
// ---------------------------------------------------------------------------
__global__ void tanhu_kernel(const float* __restrict__ X,
                             const float* __restrict__ mc) {
    int idx = blockIdx.x * blockDim.x + threadIdx.x;
    if (idx >= T_STEPS * IN_DIM) return;
    int t  = idx >> 10;
    int ci = idx & 1023;
    float v = X[(t << 10) + g_perm[ci]] * g_wval[ci];
    g_tanhu[idx] = tanhf(__fmul_rn(mc[ci], v));
}

// ---------------------------------------------------------------------------
// Kernel 2b: split W into bf16 hi/lo (vectorized: 8 elems/thread, 16B stores)
// ---------------------------------------------------------------------------
__global__ void wsplit_kernel(const float* __restrict__ W) {
    int idx = blockIdx.x * blockDim.x + threadIdx.x;     // 8 elems each
    if (idx >= OUT_DIM * KTOT / 8) return;
    const float4* W4 = (const float4*)W;
    float4 a = W4[idx * 2];
    float4 b = W4[idx * 2 + 1];
    float f[8] = {a.x, a.y, a.z, a.w, b.x, b.y, b.z, b.w};
    __nv_bfloat16 hi[8], lo[8];
#pragma unroll
    for (int i = 0; i < 8; ++i) {
        hi[i] = __float2bfloat16(f[i]);
        lo[i] = __float2bfloat16(f[i] - __bfloat162float(hi[i]));
    }
    ((uint4*)g_Whi)[idx] = *(uint4*)hi;
    ((uint4*)g_Wlo)[idx] = *(uint4*)lo;
}

// ---------------------------------------------------------------------------
// Kernel 3: persistent reservoir scan.
// 128 blocks x 512 threads; block b owns rows 2b, 2b+1; 1 thread/pixel.
// Sync protocol: each (row, 32-px chunk) publishes a single 64-bit word
// (tag<<32 | ballot).  Readers poll the word directly: tag detect + payload
// in ONE L2 round trip.  No flags, no fences.  Double-buffered by parity;
// smem halo staging double-buffered too -> ONE __syncthreads per step.
// ---------------------------------------------------------------------------
__global__ void __launch_bounds__(512, 1)
scan_kernel(const float* __restrict__ mask_fine) {
    const int b    = blockIdx.x;
    const int tid  = threadIdx.x;
    const int dy   = tid >> 8;
    const int x    = tid & 255;
    const int y    = (b << 1) + dy;
    const int ci   = ((y >> 3) << 5) + (x >> 3);
    const float mf = mask_fine[(y << 8) + x];
    const int w    = tid >> 5;           // warp 0..15
    const int lane = tid & 31;

    __shared__ unsigned sS[2][18][8];    // [smem parity][halo row k][chunk]

    // circular 1-D window params (depend only on x)
    const int b5 = (x - 2) & 255, w5 = b5 >> 5, o5 = b5 & 31, w5b = (w5 + 1) & 7;
    const int b9 = (x - 8) & 255, w9 = b9 >> 5, o9 = b9 & 31, w9b = (w9 + 1) & 7;
    const int krow = 8 + dy;

    // halo assignment: warp w<8 -> row y0-8+w (k=w); w>=8 -> row y0+2+(w-8) (k=w+2)
    int hk, hrow;
    if (w < 8) { hk = w;     hrow = ((b << 1) - 8 + w) & 255; }
    else       { hk = w + 2; hrow = ((b << 1) - 6 + w) & 255; }
    volatile unsigned long long* hp0 = &g_S64[0][hrow][lane & 7];
    volatile unsigned long long* hp1 = &g_S64[1][hrow][lane & 7];

    // prefill own rows of smem buffer 0 with S(-1)=0
    if (lane == 0) sS[0][8 + (w >> 3)][w & 7] = 0u;

    float V = 0.0f;
    const int pix = (y << 8) + x;

    for (int t = 0; t < T_STEPS; ++t) {
        // independent work first
        float u  = __fmul_rn(mf, __ldg(&g_tanhu[(t << 10) + ci]));
        float Vd = __fadd_rn(__fmul_rn(0.9f, V), __fmul_rn(0.5f, u));

        const int sb = t & 1;
        // halo: poll tagged word (tag>=t) and stage payload; one L2 RT total
        if (lane < 8) {
            volatile unsigned long long* p = (t & 1) ? hp0 : hp1;  // parity (t-1)&1
            unsigned long long v = *p;
            while ((unsigned)(v >> 32) < (unsigned)t) v = *p;
            sS[sb][hk][lane] = (unsigned)v;
        }
        __syncthreads();   // the ONLY barrier per step

        // exact integer lateral sums via popcount
        int n5 = 0;
#pragma unroll
        for (int d = -2; d <= 2; ++d) {
            unsigned v = __funnelshift_r(sS[sb][krow + d][w5], sS[sb][krow + d][w5b], o5);
            n5 += __popc(v & 0x1Fu);
        }
        int n9 = 0;
#pragma unroll
        for (int d = -8; d <= 8; d += 2) {
            unsigned v = __funnelshift_r(sS[sb][krow + d][w9], sS[sb][krow + d][w9b], o9);
            n9 += __popc(v & 0x15555u);
        }
        float c5  = __fmul_rn((float)n5, 1.0f / 25.0f);
        float c9  = __fmul_rn((float)n9, 1.0f / 81.0f);
        float lat = __fadd_rn(c5, __fmul_rn(-0.5f, c9));

        // membrane update (reference op order)
        float Vn = Vd;
        if (Vd >= 0.1f)
            Vn = __fadd_rn(__fadd_rn(Vd, __fmul_rn(0.5f, u)), lat);
        Vn = fminf(Vn, 1.0f);
        bool Sb = (Vn > 0.75f);
        if (Sb) Vn = 0.0f;
        V = Vn;

        // publish: single tagged 64-bit store (atomic word: tag + payload)
        unsigned ball = __ballot_sync(0xffffffffu, Sb);
        if (lane == 0) {
            unsigned long long pk =
                ((unsigned long long)(unsigned)(t + 1) << 32) | (unsigned long long)ball;
            *(volatile unsigned long long*)&g_S64[t & 1][y][w & 7] = pk;
            sS[sb ^ 1][8 + dy][w & 7] = ball;   // own rows for next step
        }

        // stream split-precision outputs (off the critical path)
        __nv_bfloat16 vh = __float2bfloat16(Vn);
        float vlo = Vn - __bfloat162float(vh);
        size_t obase = (size_t)t * KTOT + pix;
        g_Ahi[obase]        = vh;
        g_Ahi[obase + NPIX] = Sb ? __float2bfloat16(1.0f) : __float2bfloat16(0.0f);
        g_Alo[obase]        = __float2bfloat16(vlo);   // S-lo region never written: stays 0
    }
}

// ---------------------------------------------------------------------------
// Kernel 4: bf16 HMMA split-K GEMM via ldmatrix + mma.sync (sm_103-safe).
// grid = (4 M-tiles, 40 segments/slices).  BM=128, BN=128, BK=32, 256 thr,
// warp tile 32x64, double-buffered cp.async, padded smem (stride 40 bf16).
// ---------------------------------------------------------------------------
__global__ void __launch_bounds__(256)
mma_gemm_kernel() {
    __shared__ __nv_bfloat16 sA[2][BM][BK + 8];
    __shared__ __nv_bfloat16 sB[2][BN][BK + 8];

    const int mt = blockIdx.x;           // 0..3
    const int s  = blockIdx.y;           // 0..39
    int seg, slice;
    if (s < 16)      { seg = 0; slice = s; }
    else if (s < 32) { seg = 1; slice = s - 16; }
    else             { seg = 2; slice = s - 32; }    // only V-region slices
    const size_t k0 = (size_t)slice * GSLICE;

    const __nv_bfloat16* Abase = (seg == 2) ? g_Alo : g_Ahi;
    const __nv_bfloat16* Bbase = (seg == 1) ? g_Wlo : g_Whi;

    const int tid  = threadIdx.x;
    const int wid  = tid >> 5;
    const int lane = tid & 31;
    const int wm   = wid >> 1;           // 0..3  -> rows wm*32
    const int wn   = wid & 1;            // 0..1  -> cols wn*64

    const int lrow = tid >> 1;
    const int lch  = (tid & 1) << 1;     // chunk index 0 or 2 (each 8 bf16)
    const __nv_bfloat16* gA = Abase + (size_t)(mt * BM + lrow) * KTOT + k0 + lch * 8;
    const __nv_bfloat16* gB = Bbase + (size_t)lrow * KTOT + k0 + lch * 8;
    const uint32_t sA0 = smem_u32(&sA[0][0][0]);
    const uint32_t sB0 = smem_u32(&sB[0][0][0]);
    const uint32_t bufBytes = (uint32_t)BM * (BK + 8) * 2;
    const uint32_t rowOffA = ((uint32_t)lrow * (BK + 8) + lch * 8) * 2;
    const uint32_t rowOffB = rowOffA;

    const int aRow = wm * 32 + (lane & 15);
    const int aK   = (lane >> 4) << 3;
    const int bRow = wn * 64 + (lane & 7) + ((lane >> 4) << 3);
    const int bK   = ((lane >> 3) & 1) << 3;

    float d[2][8][4];
#pragma unroll
    for (int mi = 0; mi < 2; ++mi)
#pragma unroll
        for (int ni = 0; ni < 8; ++ni)
#pragma unroll
            for (int r = 0; r < 4; ++r) d[mi][ni][r] = 0.0f;

    {
        cp_async16(sA0 + rowOffA, gA);
        cp_async16(sA0 + rowOffA + 16, gA + 8);
        cp_async16(sB0 + rowOffB, gB);
        cp_async16(sB0 + rowOffB + 16, gB + 8);
        cp_commit();
    }

    for (int it = 0; it < KITERS; ++it) {
        const int cb = it & 1;
        if (it + 1 < KITERS) {
            const int nb = (it + 1) & 1;
            const __nv_bfloat16* ga = gA + (size_t)(it + 1) * BK;
            const __nv_bfloat16* gb = gB + (size_t)(it + 1) * BK;
            cp_async16(sA0 + nb * bufBytes + rowOffA, ga);
            cp_async16(sA0 + nb * bufBytes + rowOffA + 16, ga + 8);
            cp_async16(sB0 + nb * bufBytes + rowOffB, gb);
            cp_async16(sB0 + nb * bufBytes + rowOffB + 16, gb + 8);
            cp_commit();
            cp_wait1();
        } else {
            cp_wait0();
        }
        __syncthreads();

#pragma unroll
        for (int ks = 0; ks < 2; ++ks) {
            const int kc = ks * 16;
            uint32_t a[2][4], bf[4][4];
#pragma unroll
            for (int mi = 0; mi < 2; ++mi) {
                uint32_t addr = sA0 + cb * bufBytes +
                    ((uint32_t)(aRow + mi * 16) * (BK + 8) + kc + aK) * 2;
                ldsm_x4(a[mi][0], a[mi][1], a[mi][2], a[mi][3], addr);
            }
#pragma unroll
            for (int g = 0; g < 4; ++g) {
                uint32_t addr = sB0 + cb * bufBytes +
                    ((uint32_t)(bRow + g * 16) * (BK + 8) + kc + bK) * 2;
                ldsm_x4(bf[g][0], bf[g][1], bf[g][2], bf[g][3], addr);
            }
#pragma unroll
            for (int mi = 0; mi < 2; ++mi)
#pragma unroll
                for (int g = 0; g < 4; ++g) {
                    mma_bf16(d[mi][g * 2 + 0], a[mi], &bf[g][0]);
                    mma_bf16(d[mi][g * 2 + 1], a[mi], &bf[g][2]);
                }
        }
        __syncthreads();
    }

#pragma unroll
    for (int mi = 0; mi < 2; ++mi) {
        const int m0 = mt * BM + wm * 32 + mi * 16 + (lane >> 2);
#pragma unroll
        for (int ni = 0; ni < 8; ++ni) {
            const int col = wn * 64 + ni * 8 + (lane & 3) * 2;
            float2 v01 = make_float2(d[mi][ni][0], d[mi][ni][1]);
            float2 v23 = make_float2(d[mi][ni][2], d[mi][ni][3]);
            *reinterpret_cast<float2*>(
                &g_part[((size_t)s * T_STEPS + m0) * OUT_DIM + col]) = v01;
            *reinterpret_cast<float2*>(
                &g_part[((size_t)s * T_STEPS + m0 + 8) * OUT_DIM + col]) = v23;
        }
    }
}

// ---------------------------------------------------------------------------
// Kernel 5: deterministic split-K reduction + bias
// ---------------------------------------------------------------------------
__global__ void reduce_kernel(const float* __restrict__ b_out,
                              float* __restrict__ out) {
    int i = blockIdx.x * blockDim.x + threadIdx.x;
    if (i >= T_STEPS * OUT_DIM) return;
    int o = i & (OUT_DIM - 1);
    float sum = 0.0f;
#pragma unroll 8
    for (int ks = 0; ks < NSEG_TOT; ++ks)
        sum += g_part[(size_t)ks * (T_STEPS * OUT_DIM) + i];
    out[i] = sum + b_out[o];
}

// ---------------------------------------------------------------------------
// Launch
// ---------------------------------------------------------------------------
extern "C" void kernel_launch(void* const* d_in, const int* in_sizes, int n_in,
                              void* d_out, int out_size) {
    const float* X  = (const float*)d_in[0];   // [512,1024]
    const float* We = (const float*)d_in[1];   // [1024,1024]
    const float* mc = (const float*)d_in[2];   // [1,1,32,32]
    const float* mf = (const float*)d_in[3];   // [1,1,256,256]
    const float* W  = (const float*)d_in[4];   // [128,2,256,256]
    const float* bo = (const float*)d_in[5];   // [128]
    float* out = (float*)d_out;                // [512,128]

    init_kernel<<<16, 256>>>();
    perm_kernel<<<IN_DIM, 256>>>(We);
    tanhu_kernel<<<(T_STEPS * IN_DIM + 255) / 256, 256>>>(X, mc);
    wsplit_kernel<<<(OUT_DIM * KTOT / 8 + 255) / 256, 256>>>(W);
    scan_kernel<<<128, 512>>>(mf);
    dim3 ggrid(4, NSEG_TOT);
    mma_gemm_kernel<<<ggrid, 256>>>();
    reduce_kernel<<<(T_STEPS * OUT_DIM + 255) / 256, 256>>>(bo, out);
}